// round 13
// baseline (speedup 1.0000x reference)
#include <cuda_runtime.h>
#include <cstdint>

#define IMW   1024
#define IMH   1024
#define HW    (1024*1024)
#define BATCH 16
#define NPIX  (16u*1024u*1024u)
#define WPR   32                        // 32-bit words per row (1024/32)
#define TOTAL_WORDS (BATCH * IMH * WPR) // 524288 packed words
#define MAIN_BLOCKS 1036                // 148 SMs * 7 blocks, ONE wave

// ---------------- device scratch (static; no allocations) ----------------
__device__ double        g_acc[4];                 // A0, B0, A1, B1
__device__ unsigned int  g_E;                      // edge pixel count
__device__ unsigned int  g_ticket;                 // last-block ticket
__device__ unsigned int  g_tbits[TOTAL_WORDS];     // packed target     (2 MB)
__device__ unsigned int  g_hand [TOTAL_WORDS];     // horizontal AND-11 (2 MB)
__device__ unsigned int  g_hor  [TOTAL_WORDS];     // horizontal OR-11  (2 MB)
__device__ unsigned int  g_ebits[TOTAL_WORDS];     // packed edge mask  (2 MB)

// ---------------- kernel 1a: pack + horizontal 11-tap AND/OR --------------
// Direct ballot packing: iteration j, lane L loads pixel (base + 32j + L)
// as one int (128B coalesced per warp); ballot(v!=0) IS packed word j.
// No bit-reassembly ALU at all.
__global__ __launch_bounds__(256) void edge_h_kernel(const int* __restrict__ target) {
    __shared__ unsigned sp[256];
    const int tid  = threadIdx.x;
    const int lane = tid & 31;
    const int warp = tid >> 5;
    const int gw0  = blockIdx.x * 256;             // first word of this block
    // warp w owns words [w*32, w*32+32) = pixels [w*1024, (w+1)*1024)
    const int* pb = target + (size_t)gw0 * 32 + (size_t)warp * 1024 + lane;

    unsigned myw = 0u;
    #pragma unroll
    for (int j = 0; j < 32; j++) {
        const int v = __ldcs(pb + j * 32);
        const unsigned b = __ballot_sync(0xffffffffu, v != 0);
        if (lane == j) myw = b;                    // lane j keeps word j
    }
    sp[tid] = myw;
    __syncthreads();

    // horizontal 11-tap AND/OR (neighbors within the row; image edges pad 0)
    const int g  = gw0 + tid;
    const int wc = g & 31;
    const unsigned w = myw;
    const unsigned l = (wc > 0)  ? sp[tid - 1] : 0u;
    const unsigned r = (wc < 31) ? sp[tid + 1] : 0u;
    unsigned a = w, o = w;
    #pragma unroll
    for (int k = 1; k <= 5; k++) {
        const unsigned sr = __funnelshift_r(w, r, k);
        const unsigned sl = __funnelshift_l(l, w, k);
        a &= (sr & sl);
        o |= (sr | sl);
    }
    g_tbits[g] = w;
    g_hand[g]  = a;
    g_hor[g]   = o;
}

// ---------------- kernel 1b: vertical 11-row combine + edge count ---------
__global__ __launch_bounds__(256) void edge_v_kernel() {
    const int tid = threadIdx.x;
    const int g   = blockIdx.x * 256 + tid;
    const int r   = (g >> 5) & (IMH - 1);          // row within image

    unsigned vA = 0xffffffffu, vO = 0u;
    #pragma unroll
    for (int k = -5; k <= 5; k++) {
        const int rr = r + k;
        if (rr >= 0 && rr < IMH) {
            vA &= g_hand[g + k * WPR];
            vO |= g_hor [g + k * WPR];
        } else {
            vA = 0u;                               // zero pad: AND fails
        }
    }
    const unsigned t = g_tbits[g];
    const unsigned e = (t & ~vA) | (~t & vO);
    g_ebits[g] = e;

    unsigned c = __popc(e);
    #pragma unroll
    for (int off = 16; off > 0; off >>= 1)
        c += __shfl_down_sync(0xffffffffu, c, off);
    __shared__ unsigned wsum[8];
    const int lane = tid & 31, warp = tid >> 5;
    if (lane == 0) wsum[warp] = c;
    __syncthreads();
    if (tid == 0) {
        unsigned s = 0u;
        #pragma unroll
        for (int i = 0; i < 8; i++) s += wsum[i];
        atomicAdd(&g_E, s);
    }
}

// ---------------- kernel 2: fused log-softmax + reductions + finalize -----
// With d = x1-x0, sp = softplus(d) = max(d,0)+log1p(exp(-|d|)):
//   lpt             = t*d - sp
//   lp0+lp1-1.5*lpt = d*(1-1.5t) - 0.5*sp
__device__ __forceinline__ void proc_px(float x0, float x1, float tf, float ef,
                                        float& A, float& B) {
    const float d  = x1 - x0;
    const float sp = fmaxf(d, 0.f) + __logf(1.f + __expf(-fabsf(d)));
    A = fmaf(tf, d, A) - sp;
    B = fmaf(ef, fmaf(d, fmaf(-1.5f, tf, 1.f), -0.5f * sp), B);
}

__device__ __forceinline__ void proc_chunk(const float* __restrict__ s0,
                                           const float* __restrict__ s1,
                                           unsigned p,
                                           float& A0, float& B0,
                                           float& A1, float& B1) {
    const unsigned b   = p >> 20;          // p / HW
    const unsigned pix = p & (HW - 1u);
    const size_t base  = (size_t)b * 2u * HW + pix;

    const float4 x0 = __ldcs((const float4*)(s0 + base));
    const float4 y0 = __ldcs((const float4*)(s0 + base + HW));
    const float4 x1 = __ldcs((const float4*)(s1 + base));
    const float4 y1 = __ldcs((const float4*)(s1 + base + HW));

    const unsigned sh = p & 31u;
    const unsigned ew = g_ebits[p >> 5] >> sh;
    const unsigned tw = g_tbits[p >> 5] >> sh;

    const float t0 = (float)( tw       & 1u), e0 = (float)( ew       & 1u);
    const float t1 = (float)((tw >> 1) & 1u), e1 = (float)((ew >> 1) & 1u);
    const float t2 = (float)((tw >> 2) & 1u), e2 = (float)((ew >> 2) & 1u);
    const float t3 = (float)((tw >> 3) & 1u), e3 = (float)((ew >> 3) & 1u);

    proc_px(x0.x, y0.x, t0, e0, A0, B0);
    proc_px(x0.y, y0.y, t1, e1, A0, B0);
    proc_px(x0.z, y0.z, t2, e2, A0, B0);
    proc_px(x0.w, y0.w, t3, e3, A0, B0);

    proc_px(x1.x, y1.x, t0, e0, A1, B1);
    proc_px(x1.y, y1.y, t1, e1, A1, B1);
    proc_px(x1.z, y1.z, t2, e2, A1, B1);
    proc_px(x1.w, y1.w, t3, e3, A1, B1);
}

__global__ __launch_bounds__(256, 7) void main_kernel(const float* __restrict__ s0,
                                                      const float* __restrict__ s1,
                                                      float* __restrict__ out) {
    float A0 = 0.f, B0 = 0.f, A1 = 0.f, B1 = 0.f;
    const unsigned nch    = NPIX / 4u;                 // 4-pixel chunks
    const unsigned stride = MAIN_BLOCKS * 256u;
    unsigned c = blockIdx.x * 256u + threadIdx.x;

    for (; c + stride < nch; c += 2u * stride) {
        proc_chunk(s0, s1, c * 4u,            A0, B0, A1, B1);
        proc_chunk(s0, s1, (c + stride) * 4u, A0, B0, A1, B1);
    }
    if (c < nch) proc_chunk(s0, s1, c * 4u, A0, B0, A1, B1);

    #pragma unroll
    for (int off = 16; off > 0; off >>= 1) {
        A0 += __shfl_down_sync(0xffffffffu, A0, off);
        B0 += __shfl_down_sync(0xffffffffu, B0, off);
        A1 += __shfl_down_sync(0xffffffffu, A1, off);
        B1 += __shfl_down_sync(0xffffffffu, B1, off);
    }
    __shared__ float red[8][4];
    const int lane = threadIdx.x & 31, warp = threadIdx.x >> 5;
    if (lane == 0) { red[warp][0] = A0; red[warp][1] = B0; red[warp][2] = A1; red[warp][3] = B1; }
    __syncthreads();
    __shared__ bool is_last;
    if (threadIdx.x == 0) {
        double a0 = 0, b0 = 0, a1 = 0, b1 = 0;
        #pragma unroll
        for (int i = 0; i < 8; i++) {
            a0 += (double)red[i][0]; b0 += (double)red[i][1];
            a1 += (double)red[i][2]; b1 += (double)red[i][3];
        }
        atomicAdd(&g_acc[0], a0);
        atomicAdd(&g_acc[1], b0);
        atomicAdd(&g_acc[2], a1);
        atomicAdd(&g_acc[3], b1);
        __threadfence();
        const unsigned t = atomicAdd(&g_ticket, 1u);
        is_last = (t == (unsigned)MAIN_BLOCKS - 1u);
    }
    __syncthreads();

    if (is_last && threadIdx.x == 0) {
        const double N = (double)NPIX;
        double alpha = (double)g_E / N;
        if (alpha > 0.2) alpha = 0.2;
        const double l0 = -(g_acc[0] + alpha * g_acc[1]) / N;
        const double l1 = -(g_acc[2] + alpha * g_acc[3]) / N;
        out[0] = (float)(l0 + 0.5 * l1);
        g_acc[0] = 0.0; g_acc[1] = 0.0; g_acc[2] = 0.0; g_acc[3] = 0.0;
        g_E = 0u;
        __threadfence();
        g_ticket = 0u;
    }
}

// ---------------- launch ---------------------------------------------------
extern "C" void kernel_launch(void* const* d_in, const int* in_sizes, int n_in,
                              void* d_out, int out_size) {
    const float* s0  = (const float*)d_in[0];
    const float* s1  = (const float*)d_in[1];
    const int*   tgt = (const int*)d_in[2];

    edge_h_kernel<<<TOTAL_WORDS / 256, 256>>>(tgt);
    edge_v_kernel<<<TOTAL_WORDS / 256, 256>>>();
    main_kernel<<<MAIN_BLOCKS, 256>>>(s0, s1, (float*)d_out);
}

// round 15
// speedup vs baseline: 1.0033x; 1.0033x over previous
#include <cuda_runtime.h>
#include <cstdint>

#define IMW   1024
#define IMH   1024
#define HW    (1024*1024)
#define BATCH 16
#define NPIX  (16u*1024u*1024u)
#define WPR   32                        // 32-bit words per row (1024/32)
#define TOTAL_WORDS (BATCH * IMH * WPR) // 524288 packed words
#define MAIN_BLOCKS 888                 // 148 SMs * 6 blocks, ONE wave

// ---------------- device scratch (static; no allocations) ----------------
__device__ double        g_acc[4];                 // A0, B0, A1, B1
__device__ unsigned int  g_E;                      // edge pixel count
__device__ unsigned int  g_ticket;                 // last-block ticket
__device__ unsigned int  g_tbits[TOTAL_WORDS];     // packed target     (2 MB)
__device__ unsigned int  g_hand [TOTAL_WORDS];     // horizontal AND-11 (2 MB)
__device__ unsigned int  g_hor  [TOTAL_WORDS];     // horizontal OR-11  (2 MB)
__device__ unsigned int  g_ebits[TOTAL_WORDS];     // packed edge mask  (2 MB)

// ---------------- kernel 1a: pack + horizontal 11-tap AND/OR --------------
// Direct ballot packing: iteration j, lane L loads pixel (base + 32j + L)
// as one int (128B coalesced per warp); ballot(v!=0) IS packed word j.
// Loads batched 8 at a time into registers to guarantee MLP=8.
__global__ __launch_bounds__(256) void edge_h_kernel(const int* __restrict__ target) {
    __shared__ unsigned sp[256];
    const int tid  = threadIdx.x;
    const int lane = tid & 31;
    const int warp = tid >> 5;
    const int gw0  = blockIdx.x * 256;             // first word of this block
    // warp w owns words [w*32, w*32+32) = pixels [w*1024, (w+1)*1024)
    const int* pb = target + (size_t)gw0 * 32 + (size_t)warp * 1024 + lane;

    unsigned myw = 0u;
    #pragma unroll
    for (int jj = 0; jj < 4; jj++) {
        int v[8];
        #pragma unroll
        for (int k = 0; k < 8; k++)                 // 8 independent loads
            v[k] = __ldcs(pb + (jj * 8 + k) * 32);
        #pragma unroll
        for (int k = 0; k < 8; k++) {
            const unsigned b = __ballot_sync(0xffffffffu, v[k] != 0);
            if (lane == jj * 8 + k) myw = b;        // lane j keeps word j
        }
    }
    sp[tid] = myw;
    __syncthreads();

    // horizontal 11-tap AND/OR (neighbors within the row; image edges pad 0)
    const int g  = gw0 + tid;
    const int wc = g & 31;
    const unsigned w = myw;
    const unsigned l = (wc > 0)  ? sp[tid - 1] : 0u;
    const unsigned r = (wc < 31) ? sp[tid + 1] : 0u;
    unsigned a = w, o = w;
    #pragma unroll
    for (int k = 1; k <= 5; k++) {
        const unsigned sr = __funnelshift_r(w, r, k);
        const unsigned sl = __funnelshift_l(l, w, k);
        a &= (sr & sl);
        o |= (sr | sl);
    }
    g_tbits[g] = w;
    g_hand[g]  = a;
    g_hor[g]   = o;
}

// ---------------- kernel 1b: vertical 11-row combine + edge count ---------
__global__ __launch_bounds__(256) void edge_v_kernel() {
    const int tid = threadIdx.x;
    const int g   = blockIdx.x * 256 + tid;
    const int r   = (g >> 5) & (IMH - 1);          // row within image

    unsigned vA = 0xffffffffu, vO = 0u;
    #pragma unroll
    for (int k = -5; k <= 5; k++) {
        const int rr = r + k;
        if (rr >= 0 && rr < IMH) {
            vA &= g_hand[g + k * WPR];
            vO |= g_hor [g + k * WPR];
        } else {
            vA = 0u;                               // zero pad: AND fails
        }
    }
    const unsigned t = g_tbits[g];
    const unsigned e = (t & ~vA) | (~t & vO);
    g_ebits[g] = e;

    unsigned c = __popc(e);
    #pragma unroll
    for (int off = 16; off > 0; off >>= 1)
        c += __shfl_down_sync(0xffffffffu, c, off);
    __shared__ unsigned wsum[8];
    const int lane = tid & 31, warp = tid >> 5;
    if (lane == 0) wsum[warp] = c;
    __syncthreads();
    if (tid == 0) {
        unsigned s = 0u;
        #pragma unroll
        for (int i = 0; i < 8; i++) s += wsum[i];
        atomicAdd(&g_E, s);
    }
}

// ---------------- kernel 2: fused log-softmax + reductions + finalize -----
// With d = x1-x0, sp = softplus(d) = max(d,0)+log1p(exp(-|d|)):
//   lpt             = t*d - sp
//   lp0+lp1-1.5*lpt = d*(1-1.5t) - 0.5*sp
__device__ __forceinline__ void proc_px(float x0, float x1, float tf, float ef,
                                        float& A, float& B) {
    const float d  = x1 - x0;
    const float sp = fmaxf(d, 0.f) + __logf(1.f + __expf(-fabsf(d)));
    A = fmaf(tf, d, A) - sp;
    B = fmaf(ef, fmaf(d, fmaf(-1.5f, tf, 1.f), -0.5f * sp), B);
}

__device__ __forceinline__ void proc_chunk(const float* __restrict__ s0,
                                           const float* __restrict__ s1,
                                           unsigned p,
                                           float& A0, float& B0,
                                           float& A1, float& B1) {
    const unsigned b   = p >> 20;          // p / HW
    const unsigned pix = p & (HW - 1u);
    const size_t base  = (size_t)b * 2u * HW + pix;

    const float4 x0 = __ldcs((const float4*)(s0 + base));
    const float4 y0 = __ldcs((const float4*)(s0 + base + HW));
    const float4 x1 = __ldcs((const float4*)(s1 + base));
    const float4 y1 = __ldcs((const float4*)(s1 + base + HW));

    const unsigned sh = p & 31u;
    const unsigned ew = g_ebits[p >> 5] >> sh;
    const unsigned tw = g_tbits[p >> 5] >> sh;

    const float t0 = (float)( tw       & 1u), e0 = (float)( ew       & 1u);
    const float t1 = (float)((tw >> 1) & 1u), e1 = (float)((ew >> 1) & 1u);
    const float t2 = (float)((tw >> 2) & 1u), e2 = (float)((ew >> 2) & 1u);
    const float t3 = (float)((tw >> 3) & 1u), e3 = (float)((ew >> 3) & 1u);

    proc_px(x0.x, y0.x, t0, e0, A0, B0);
    proc_px(x0.y, y0.y, t1, e1, A0, B0);
    proc_px(x0.z, y0.z, t2, e2, A0, B0);
    proc_px(x0.w, y0.w, t3, e3, A0, B0);

    proc_px(x1.x, y1.x, t0, e0, A1, B1);
    proc_px(x1.y, y1.y, t1, e1, A1, B1);
    proc_px(x1.z, y1.z, t2, e2, A1, B1);
    proc_px(x1.w, y1.w, t3, e3, A1, B1);
}

__global__ __launch_bounds__(256, 6) void main_kernel(const float* __restrict__ s0,
                                                      const float* __restrict__ s1,
                                                      float* __restrict__ out) {
    float A0 = 0.f, B0 = 0.f, A1 = 0.f, B1 = 0.f;
    const unsigned nch    = NPIX / 4u;                 // 4-pixel chunks
    const unsigned stride = MAIN_BLOCKS * 256u;
    unsigned c = blockIdx.x * 256u + threadIdx.x;

    for (; c + stride < nch; c += 2u * stride) {
        proc_chunk(s0, s1, c * 4u,            A0, B0, A1, B1);
        proc_chunk(s0, s1, (c + stride) * 4u, A0, B0, A1, B1);
    }
    if (c < nch) proc_chunk(s0, s1, c * 4u, A0, B0, A1, B1);

    #pragma unroll
    for (int off = 16; off > 0; off >>= 1) {
        A0 += __shfl_down_sync(0xffffffffu, A0, off);
        B0 += __shfl_down_sync(0xffffffffu, B0, off);
        A1 += __shfl_down_sync(0xffffffffu, A1, off);
        B1 += __shfl_down_sync(0xffffffffu, B1, off);
    }
    __shared__ float red[8][4];
    const int lane = threadIdx.x & 31, warp = threadIdx.x >> 5;
    if (lane == 0) { red[warp][0] = A0; red[warp][1] = B0; red[warp][2] = A1; red[warp][3] = B1; }
    __syncthreads();
    __shared__ bool is_last;
    if (threadIdx.x == 0) {
        double a0 = 0, b0 = 0, a1 = 0, b1 = 0;
        #pragma unroll
        for (int i = 0; i < 8; i++) {
            a0 += (double)red[i][0]; b0 += (double)red[i][1];
            a1 += (double)red[i][2]; b1 += (double)red[i][3];
        }
        atomicAdd(&g_acc[0], a0);
        atomicAdd(&g_acc[1], b0);
        atomicAdd(&g_acc[2], a1);
        atomicAdd(&g_acc[3], b1);
        __threadfence();
        const unsigned t = atomicAdd(&g_ticket, 1u);
        is_last = (t == (unsigned)MAIN_BLOCKS - 1u);
    }
    __syncthreads();

    if (is_last && threadIdx.x == 0) {
        const double N = (double)NPIX;
        double alpha = (double)g_E / N;
        if (alpha > 0.2) alpha = 0.2;
        const double l0 = -(g_acc[0] + alpha * g_acc[1]) / N;
        const double l1 = -(g_acc[2] + alpha * g_acc[3]) / N;
        out[0] = (float)(l0 + 0.5 * l1);
        g_acc[0] = 0.0; g_acc[1] = 0.0; g_acc[2] = 0.0; g_acc[3] = 0.0;
        g_E = 0u;
        __threadfence();
        g_ticket = 0u;
    }
}

// ---------------- launch ---------------------------------------------------
extern "C" void kernel_launch(void* const* d_in, const int* in_sizes, int n_in,
                              void* d_out, int out_size) {
    const float* s0  = (const float*)d_in[0];
    const float* s1  = (const float*)d_in[1];
    const int*   tgt = (const int*)d_in[2];

    edge_h_kernel<<<TOTAL_WORDS / 256, 256>>>(tgt);
    edge_v_kernel<<<TOTAL_WORDS / 256, 256>>>();
    main_kernel<<<MAIN_BLOCKS, 256>>>(s0, s1, (float*)d_out);
}